// round 13
// baseline (speedup 1.0000x reference)
#include <cuda_runtime.h>

// ConformalMetric: R = -2*exp(-2*Phi) * (lap(Phi) + 2*|grad(Phi)|^2)
// Phi = phi_pos - lambda*phi_neg, edge-clamped 6-point stencil, h=1.
// Shape (B,H,W,D) = (4,128,128,128), D contiguous.
//
// Round-13: R9 champion body (16.83us), single variable changed: CH 4 -> 8.
// Halves wave count (1024 blocks = 1.38 waves vs 2.77) and halves the
// per-block prologue overhead (3 prologue plane-loads amortized over 8
// marched planes instead of 4). Everything else identical: barrier-free
// H-march, prefetched center plane, 6 independent LDG.128/step, packed
// f32x2 math, 48 regs / 40 warps, streaming stores.

#define Bn 4
#define Hn 128
#define Wn 128
#define Dn 128
#define WSLAB 8     // W rows per block
#define CH 8        // H planes marched per block

typedef unsigned long long u64;

__device__ __forceinline__ u64 pk2(float lo, float hi) {
    u64 r; asm("mov.b64 %0, {%1, %2};" : "=l"(r) : "f"(lo), "f"(hi)); return r;
}
__device__ __forceinline__ void upk2(u64 v, float& lo, float& hi) {
    asm("mov.b64 {%0, %1}, %2;" : "=f"(lo), "=f"(hi) : "l"(v));
}
__device__ __forceinline__ u64 fma2(u64 a, u64 b, u64 c) {
    u64 r; asm("fma.rn.f32x2 %0, %1, %2, %3;" : "=l"(r) : "l"(a), "l"(b), "l"(c)); return r;
}
__device__ __forceinline__ u64 add2(u64 a, u64 b) {
    u64 r; asm("add.rn.f32x2 %0, %1, %2;" : "=l"(r) : "l"(a), "l"(b)); return r;
}
__device__ __forceinline__ u64 mul2(u64 a, u64 b) {
    u64 r; asm("mul.rn.f32x2 %0, %1, %2;" : "=l"(r) : "l"(a), "l"(b)); return r;
}
__device__ __forceinline__ float ex2f(float x) {
    float r; asm("ex2.approx.f32 %0, %1;" : "=f"(r) : "f"(x)); return r;
}

struct P4 { u64 lo, hi; };   // 4 floats as two packed f32x2 (elems 0,1 | 2,3)

__global__ __launch_bounds__(256, 5) void conformal_ch8(
    const float* __restrict__ pos,
    const float* __restrict__ neg,
    const float* __restrict__ lam_p,
    float* __restrict__ out)
{
    const float lam = __ldg(lam_p);
    const u64 NEGLAM = pk2(-lam, -lam);
    const u64 NEG1   = pk2(-1.0f, -1.0f);
    const u64 NEG6   = pk2(-6.0f, -6.0f);
    const u64 HALF   = pk2(0.5f, 0.5f);
    const u64 N2L2E  = pk2(-2.8853900817779268f, -2.8853900817779268f); // -2*log2(e)
    const u64 NEG2   = pk2(-2.0f, -2.0f);

    const int tx = threadIdx.x;            // 0..31 -> d4 lane
    const int ty = threadIdx.y;            // 0..WSLAB-1 -> w row
    const int b  = blockIdx.z;
    const int h0 = blockIdx.y * CH;
    const int w  = blockIdx.x * WSLAB + ty;

    const int wm = (w > 0)      ? w - 1 : 0;
    const int wp = (w < Wn - 1) ? w + 1 : Wn - 1;

    const int base_b = b * Hn * Wn * Dn;
    const int dofs   = tx * 4;

    auto ldphi = [&](int hh, int ww) -> P4 {
        const int i = base_b + (hh * Wn + ww) * Dn + dofs;
        const ulonglong2 P = *reinterpret_cast<const ulonglong2*>(pos + i);
        const ulonglong2 N = *reinterpret_cast<const ulonglong2*>(neg + i);
        P4 r;
        r.lo = fma2(N.x, NEGLAM, P.x);     // phi = pos - lam*neg (packed)
        r.hi = fma2(N.y, NEGLAM, P.y);
        return r;
    };

    // prologue: Phi(h0-1), Phi(h0), and prefetched Phi(h0+1)
    const int hm0 = (h0 > 0) ? h0 - 1 : 0;
    P4 Cm = ldphi(hm0, w);
    P4 Cc = ldphi(h0,  w);
    P4 Cp = ldphi(h0 + 1, w);              // h0 <= Hn-CH, so h0+1 < Hn

#pragma unroll 4
    for (int hh = 0; hh < CH; ++hh) {
        const int h   = h0 + hh;
        const int hp2 = (h + 2 < Hn) ? h + 2 : Hn - 1;  // next iteration's Cp

        // Cp_next: DRAM stream, consumed next iteration (latency hidden).
        // YM/YP: L1/L2 hits, consumed this iteration.
        P4 Cpn = ldphi(hp2, w);
        P4 YM  = ldphi(h,  wm);
        P4 YP  = ldphi(h,  wp);

        // unpack center for shuffles / D-shifted pairs
        float cx, cy, cz, cw;
        upk2(Cc.lo, cx, cy);
        upk2(Cc.hi, cz, cw);

        float zm0 = __shfl_up_sync(0xffffffffu,  cw, 1);
        float zp3 = __shfl_down_sync(0xffffffffu, cx, 1);
        if (tx == 0)  zm0 = cx;   // clamp d=0
        if (tx == 31) zp3 = cw;   // clamp d=Dn-1

        // D-shifted packed vectors: zm={zm0,cx,cy,cz}, zp={cy,cz,cw,zp3}
        const u64 zm_lo = pk2(zm0, cx);
        const u64 mid   = pk2(cy, cz);     // zm.hi == zp.lo
        const u64 zp_hi = pk2(cw, zp3);

        float r0, r1, r2, r3;
#pragma unroll
        for (int half = 0; half < 2; ++half) {
            const u64 c  = half ? Cc.hi : Cc.lo;
            const u64 xm = half ? Cm.hi : Cm.lo;
            const u64 xp = half ? Cp.hi : Cp.lo;
            const u64 ym = half ? YM.hi : YM.lo;
            const u64 yp = half ? YP.hi : YP.lo;
            const u64 zm = half ? mid   : zm_lo;
            const u64 zp = half ? zp_hi : mid;

            const u64 dx = fma2(xm, NEG1, xp);           // xp - xm
            const u64 dy = fma2(ym, NEG1, yp);
            const u64 dz = fma2(zm, NEG1, zp);
            u64 sq = mul2(dz, dz);
            sq = fma2(dy, dy, sq);
            sq = fma2(dx, dx, sq);                       // sum d^2 = 4*grad_sq

            u64 lap = add2(add2(add2(xp, xm), add2(yp, ym)), add2(zp, zm));
            lap = fma2(c, NEG6, lap);                    // - 6c
            const u64 arg  = fma2(sq, HALF, lap);        // lap + 2*grad_sq
            const u64 m    = mul2(c, N2L2E);             // -2c*log2(e)
            const u64 narg = mul2(arg, NEG2);            // -2*arg

            float m0, m1, a0, a1;
            upk2(m, m0, m1);
            upk2(narg, a0, a1);
            const float e0 = ex2f(m0);                   // exp(-2c)
            const float e1 = ex2f(m1);
            if (half) { r2 = e0 * a0; r3 = e1 * a1; }
            else      { r0 = e0 * a0; r1 = e1 * a1; }
        }

        // streaming store: keep the write stream from evicting inputs
        const int oidx = base_b + (h * Wn + w) * Dn + dofs;
        __stcs(reinterpret_cast<float4*>(out + oidx),
               make_float4(r0, r1, r2, r3));

        Cm = Cc; Cc = Cp; Cp = Cpn;
    }
}

extern "C" void kernel_launch(void* const* d_in, const int* in_sizes, int n_in,
                              void* d_out, int out_size)
{
    const float* pos = (const float*)d_in[0];  // phi_positive (B,H,W,D) f32
    const float* neg = (const float*)d_in[1];  // phi_negative (B,H,W,D) f32
    const float* lam = (const float*)d_in[2];  // lambda_repulsion (1,) f32
    float* out = (float*)d_out;

    dim3 block(32, WSLAB, 1);                   // 256 threads
    dim3 grid(Wn / WSLAB, Hn / CH, Bn);         // (16, 16, 4) = 1024 blocks
    conformal_ch8<<<grid, block>>>(pos, neg, lam, out);
}

// round 14
// speedup vs baseline: 1.3788x; 1.3788x over previous
#include <cuda_runtime.h>

// ConformalMetric: R = -2*exp(-2*Phi) * (lap(Phi) + 2*|grad(Phi)|^2)
// Phi = phi_pos - lambda*phi_neg, edge-clamped 6-point stencil, h=1.
// Shape (B,H,W,D) = (4,128,128,128), D contiguous.
//
// Round-14: R9 champion body, repartitioned at fixed occupancy:
// 128-thread blocks (32 d-lanes x 4 W rows), launch_bounds(128,10)
// -> 10 CTAs x 4 warps = same 40 warps/SM, but evenly spread across
// SMSPs and with 4096 finer-grained blocks for tail smoothing.
// Barrier-free H-march, prefetched center plane, 6 independent
// LDG.128/step, packed f32x2 math, streaming stores.

#define Bn 4
#define Hn 128
#define Wn 128
#define Dn 128
#define WSLAB 4     // W rows per block
#define CH 4        // H planes marched per block

typedef unsigned long long u64;

__device__ __forceinline__ u64 pk2(float lo, float hi) {
    u64 r; asm("mov.b64 %0, {%1, %2};" : "=l"(r) : "f"(lo), "f"(hi)); return r;
}
__device__ __forceinline__ void upk2(u64 v, float& lo, float& hi) {
    asm("mov.b64 {%0, %1}, %2;" : "=f"(lo), "=f"(hi) : "l"(v));
}
__device__ __forceinline__ u64 fma2(u64 a, u64 b, u64 c) {
    u64 r; asm("fma.rn.f32x2 %0, %1, %2, %3;" : "=l"(r) : "l"(a), "l"(b), "l"(c)); return r;
}
__device__ __forceinline__ u64 add2(u64 a, u64 b) {
    u64 r; asm("add.rn.f32x2 %0, %1, %2;" : "=l"(r) : "l"(a), "l"(b)); return r;
}
__device__ __forceinline__ u64 mul2(u64 a, u64 b) {
    u64 r; asm("mul.rn.f32x2 %0, %1, %2;" : "=l"(r) : "l"(a), "l"(b)); return r;
}
__device__ __forceinline__ float ex2f(float x) {
    float r; asm("ex2.approx.f32 %0, %1;" : "=f"(r) : "f"(x)); return r;
}

struct P4 { u64 lo, hi; };   // 4 floats as two packed f32x2 (elems 0,1 | 2,3)

__global__ __launch_bounds__(128, 10) void conformal_fine(
    const float* __restrict__ pos,
    const float* __restrict__ neg,
    const float* __restrict__ lam_p,
    float* __restrict__ out)
{
    const float lam = __ldg(lam_p);
    const u64 NEGLAM = pk2(-lam, -lam);
    const u64 NEG1   = pk2(-1.0f, -1.0f);
    const u64 NEG6   = pk2(-6.0f, -6.0f);
    const u64 HALF   = pk2(0.5f, 0.5f);
    const u64 N2L2E  = pk2(-2.8853900817779268f, -2.8853900817779268f); // -2*log2(e)
    const u64 NEG2   = pk2(-2.0f, -2.0f);

    const int tx = threadIdx.x;            // 0..31 -> d4 lane
    const int ty = threadIdx.y;            // 0..WSLAB-1 -> w row
    const int b  = blockIdx.z;
    const int h0 = blockIdx.y * CH;
    const int w  = blockIdx.x * WSLAB + ty;

    const int wm = (w > 0)      ? w - 1 : 0;
    const int wp = (w < Wn - 1) ? w + 1 : Wn - 1;

    const int base_b = b * Hn * Wn * Dn;
    const int dofs   = tx * 4;

    auto ldphi = [&](int hh, int ww) -> P4 {
        const int i = base_b + (hh * Wn + ww) * Dn + dofs;
        const ulonglong2 P = *reinterpret_cast<const ulonglong2*>(pos + i);
        const ulonglong2 N = *reinterpret_cast<const ulonglong2*>(neg + i);
        P4 r;
        r.lo = fma2(N.x, NEGLAM, P.x);     // phi = pos - lam*neg (packed)
        r.hi = fma2(N.y, NEGLAM, P.y);
        return r;
    };

    // prologue: Phi(h0-1), Phi(h0), and prefetched Phi(h0+1)
    const int hm0 = (h0 > 0) ? h0 - 1 : 0;
    P4 Cm = ldphi(hm0, w);
    P4 Cc = ldphi(h0,  w);
    P4 Cp = ldphi(h0 + 1, w);              // h0 <= Hn-CH, so h0+1 < Hn

#pragma unroll
    for (int hh = 0; hh < CH; ++hh) {
        const int h   = h0 + hh;
        const int hp2 = (h + 2 < Hn) ? h + 2 : Hn - 1;  // next iteration's Cp

        // Cp_next: DRAM stream, consumed next iteration (latency hidden).
        // YM/YP: L1/L2 hits, consumed this iteration.
        P4 Cpn = ldphi(hp2, w);
        P4 YM  = ldphi(h,  wm);
        P4 YP  = ldphi(h,  wp);

        // unpack center for shuffles / D-shifted pairs
        float cx, cy, cz, cw;
        upk2(Cc.lo, cx, cy);
        upk2(Cc.hi, cz, cw);

        float zm0 = __shfl_up_sync(0xffffffffu,  cw, 1);
        float zp3 = __shfl_down_sync(0xffffffffu, cx, 1);
        if (tx == 0)  zm0 = cx;   // clamp d=0
        if (tx == 31) zp3 = cw;   // clamp d=Dn-1

        // D-shifted packed vectors: zm={zm0,cx,cy,cz}, zp={cy,cz,cw,zp3}
        const u64 zm_lo = pk2(zm0, cx);
        const u64 mid   = pk2(cy, cz);     // zm.hi == zp.lo
        const u64 zp_hi = pk2(cw, zp3);

        float r0, r1, r2, r3;
#pragma unroll
        for (int half = 0; half < 2; ++half) {
            const u64 c  = half ? Cc.hi : Cc.lo;
            const u64 xm = half ? Cm.hi : Cm.lo;
            const u64 xp = half ? Cp.hi : Cp.lo;
            const u64 ym = half ? YM.hi : YM.lo;
            const u64 yp = half ? YP.hi : YP.lo;
            const u64 zm = half ? mid   : zm_lo;
            const u64 zp = half ? zp_hi : mid;

            const u64 dx = fma2(xm, NEG1, xp);           // xp - xm
            const u64 dy = fma2(ym, NEG1, yp);
            const u64 dz = fma2(zm, NEG1, zp);
            u64 sq = mul2(dz, dz);
            sq = fma2(dy, dy, sq);
            sq = fma2(dx, dx, sq);                       // sum d^2 = 4*grad_sq

            u64 lap = add2(add2(add2(xp, xm), add2(yp, ym)), add2(zp, zm));
            lap = fma2(c, NEG6, lap);                    // - 6c
            const u64 arg  = fma2(sq, HALF, lap);        // lap + 2*grad_sq
            const u64 m    = mul2(c, N2L2E);             // -2c*log2(e)
            const u64 narg = mul2(arg, NEG2);            // -2*arg

            float m0, m1, a0, a1;
            upk2(m, m0, m1);
            upk2(narg, a0, a1);
            const float e0 = ex2f(m0);                   // exp(-2c)
            const float e1 = ex2f(m1);
            if (half) { r2 = e0 * a0; r3 = e1 * a1; }
            else      { r0 = e0 * a0; r1 = e1 * a1; }
        }

        // streaming store: keep the write stream from evicting inputs
        const int oidx = base_b + (h * Wn + w) * Dn + dofs;
        __stcs(reinterpret_cast<float4*>(out + oidx),
               make_float4(r0, r1, r2, r3));

        Cm = Cc; Cc = Cp; Cp = Cpn;
    }
}

extern "C" void kernel_launch(void* const* d_in, const int* in_sizes, int n_in,
                              void* d_out, int out_size)
{
    const float* pos = (const float*)d_in[0];  // phi_positive (B,H,W,D) f32
    const float* neg = (const float*)d_in[1];  // phi_negative (B,H,W,D) f32
    const float* lam = (const float*)d_in[2];  // lambda_repulsion (1,) f32
    float* out = (float*)d_out;

    dim3 block(32, WSLAB, 1);                   // 128 threads
    dim3 grid(Wn / WSLAB, Hn / CH, Bn);         // (32, 32, 4) = 4096 blocks
    conformal_fine<<<grid, block>>>(pos, neg, lam, out);
}